// round 9
// baseline (speedup 1.0000x reference)
#include <cuda_runtime.h>
#include <cuda_fp16.h>
#include <cstdint>

#define BATCH 4
#define SEQ   2048
#define DMODEL 1024
#define NHEADS 16
#define DK    64

// ---------------- scratch (static device globals; no allocation) ------------
__device__ __half g_Qh[BATCH * NHEADS * SEQ * DK];    // [B,H,S,Dk] fp16
__device__ __half g_Kh[BATCH * NHEADS * SEQ * DK];    // [B,H,S,Dk] fp16
__device__ __half g_Vh[BATCH * NHEADS * DK * SEQ];    // [B,H,Dk,S] fp16 (transposed)
__device__ __half g_ctxh[BATCH * SEQ * DMODEL];       // [B,S,D] fp16
__device__ __half g_xh[BATCH * SEQ * DMODEL];         // x fp16
__device__ __half g_wqt[DMODEL * DMODEL];             // [N,K] fp16 (transposed)
__device__ __half g_wkt[DMODEL * DMODEL];
__device__ __half g_wvt[DMODEL * DMODEL];
__device__ __half g_wot[DMODEL * DMODEL];

// ---------------- helpers ----------------------------------------------------
__device__ __forceinline__ void cp_async16(uint32_t smem, const void* gmem) {
    asm volatile("cp.async.ca.shared.global [%0], [%1], 16;\n"
                 :: "r"(smem), "l"(gmem));
}
#define CP_COMMIT()  asm volatile("cp.async.commit_group;\n" ::)
#define CP_WAIT(n)   asm volatile("cp.async.wait_group %0;\n" :: "n"(n))

// 128-byte bulk copy gmem -> smem, completion counted on mbarrier
__device__ __forceinline__ void bulk_cp128(uint32_t dst, const void* src, uint32_t mbar) {
    asm volatile(
        "cp.async.bulk.shared::cta.global.mbarrier::complete_tx::bytes "
        "[%0], [%1], 128, [%2];"
        :: "r"(dst), "l"(src), "r"(mbar) : "memory");
}

#define MBARRIER_INIT(a, c) \
    asm volatile("mbarrier.init.shared.b64 [%0], %1;" :: "r"(a), "r"(c) : "memory")

#define MBAR_ARRIVE_TX(a, tx) \
    asm volatile("mbarrier.arrive.expect_tx.shared.b64 _, [%0], %1;" \
                 :: "r"(a), "r"(tx) : "memory")

__device__ __forceinline__ void mbar_wait_parity(uint32_t mbar, uint32_t parity) {
    asm volatile(
        "{\n\t.reg .pred P1;\n\t"
        "WAIT_LOOP_%=:\n\t"
        "mbarrier.try_wait.parity.acquire.cta.shared::cta.b64 P1, [%0], %1, 0x989680;\n\t"
        "@P1 bra.uni WAIT_DONE_%=;\n\t"
        "bra.uni WAIT_LOOP_%=;\n\t"
        "WAIT_DONE_%=:\n\t}"
        :: "r"(mbar), "r"(parity) : "memory");
}

#define MMA_F16(d0,d1,d2,d3,a0,a1,a2,a3,b0,b1)                                  \
    asm volatile(                                                               \
        "mma.sync.aligned.m16n8k16.row.col.f32.f16.f16.f32 "                    \
        "{%0,%1,%2,%3}, {%4,%5,%6,%7}, {%8,%9}, {%0,%1,%2,%3};\n"               \
        : "+f"(d0), "+f"(d1), "+f"(d2), "+f"(d3)                                \
        : "r"(a0), "r"(a1), "r"(a2), "r"(a3), "r"(b0), "r"(b1))

// ---------------- prep kernels -----------------------------------------------
__global__ void cvt_f16_kernel(const float* __restrict__ src,
                               __half* __restrict__ dst, int n4)
{
    int i = blockIdx.x * blockDim.x + threadIdx.x;
    if (i < n4) {
        float4 v = ((const float4*)src)[i];
        __half2 h0 = __floats2half2_rn(v.x, v.y);
        __half2 h1 = __floats2half2_rn(v.z, v.w);
        uint2 u;
        u.x = *(uint32_t*)&h0;
        u.y = *(uint32_t*)&h1;
        ((uint2*)dst)[i] = u;
    }
}

// 4 weights [K,N] f32 -> [N,K] f16, z selects the matrix
__global__ void cvt_transpose4_kernel(
    const float* __restrict__ w0, const float* __restrict__ w1,
    const float* __restrict__ w2, const float* __restrict__ w3,
    __half* __restrict__ d0, __half* __restrict__ d1,
    __half* __restrict__ d2, __half* __restrict__ d3)
{
    const float* src;
    __half* dst;
    switch (blockIdx.z) {
        case 0: src = w0; dst = d0; break;
        case 1: src = w1; dst = d1; break;
        case 2: src = w2; dst = d2; break;
        default: src = w3; dst = d3; break;
    }
    __shared__ float t[32][33];
    const int bx = blockIdx.x * 32;   // n
    const int by = blockIdx.y * 32;   // k
    const int tx = threadIdx.x & 31, ty = threadIdx.x >> 5;
#pragma unroll
    for (int i = 0; i < 4; i++)
        t[ty + i * 8][tx] = src[(size_t)(by + ty + i * 8) * DMODEL + bx + tx];
    __syncthreads();
#pragma unroll
    for (int i = 0; i < 4; i++)
        dst[(size_t)(bx + ty + i * 8) * DMODEL + by + tx] =
            __float2half_rn(t[tx][ty + i * 8]);
}

// ---------------- fp16 mma GEMM (bulk-copy, 4-stage) --------------------------
// C[8192,1024] = X[8192,1024] @ Wt[1024,1024]^T + bias. CTA 128x256, kblock 64.
#define GST 72
#define GROWB 144                      // row stride bytes
#define GA_BYTES (128 * GROWB)         // 18432
#define GB_BYTES (256 * GROWB)         // 36864
#define GSTAGE (GA_BYTES + GB_BYTES)   // 55296
#define GDATA0 128                     // mbars live below
#define GNST 4
#define GSMEM (GDATA0 + GNST * GSTAGE) // 221312 B

// LAYOUT 0: fp32 out.  LAYOUT 1: Q/K fp16 scatter.  LAYOUT 2: V fp16 transposed.
template <int LAYOUT>
__device__ __forceinline__ void gemm_f16_body(
    const __half* __restrict__ X, const __half* __restrict__ Wt,
    const float* __restrict__ bias, void* __restrict__ outv)
{
    extern __shared__ __half gsmh[];
    const uint32_t smem_u32 = (uint32_t)__cvta_generic_to_shared(gsmh);

    const int tid = threadIdx.x;
    const int m0 = blockIdx.y * 128;
    const int n0 = blockIdx.x * 256;
    const int warp = tid >> 5, lane = tid & 31;
    const int g = lane >> 2, q = lane & 3;
    const int wm = (warp >> 2) * 64;
    const int wn = (warp & 3) * 64;

    if (tid == 0) {
#pragma unroll
        for (int s = 0; s < GNST; s++) MBARRIER_INIT(smem_u32 + 8 * s, 256);
    }
    __syncthreads();

    float acc[4][8][4];
#pragma unroll
    for (int i = 0; i < 4; i++)
#pragma unroll
        for (int j = 0; j < 8; j++)
#pragma unroll
            for (int c = 0; c < 4; c++) acc[i][j][c] = 0.f;

    auto issue_loads = [&](int kt) {
        const int stage = kt & 3;
        const uint32_t mb = smem_u32 + 8 * stage;
        const uint32_t base = smem_u32 + GDATA0 + stage * GSTAGE;
        const uint32_t mybytes = (tid < 128) ? 256u : 128u;
        MBAR_ARRIVE_TX(mb, mybytes);
        if (tid < 128)
            bulk_cp128(base + tid * GROWB,
                       X + (size_t)(m0 + tid) * DMODEL + kt * 64, mb);
        bulk_cp128(base + GA_BYTES + tid * GROWB,
                   Wt + (size_t)(n0 + tid) * DMODEL + kt * 64, mb);
    };

    auto compute = [&](int stage) {
        const __half* Xs = gsmh + (GDATA0 + stage * GSTAGE) / 2;
        const __half* Ws = Xs + GA_BYTES / 2;
#pragma unroll
        for (int ks = 0; ks < 4; ks++) {
            const int kc = ks * 16 + 2 * q;
            uint32_t a[4][4], b[8][2];
#pragma unroll
            for (int i = 0; i < 4; i++) {
                const int row = wm + i * 16 + g;
                a[i][0] = *(const uint32_t*)&Xs[row * GST + kc];
                a[i][1] = *(const uint32_t*)&Xs[(row + 8) * GST + kc];
                a[i][2] = *(const uint32_t*)&Xs[row * GST + kc + 8];
                a[i][3] = *(const uint32_t*)&Xs[(row + 8) * GST + kc + 8];
            }
#pragma unroll
            for (int j = 0; j < 8; j++) {
                const int col = wn + j * 8 + g;
                b[j][0] = *(const uint32_t*)&Ws[col * GST + kc];
                b[j][1] = *(const uint32_t*)&Ws[col * GST + kc + 8];
            }
#pragma unroll
            for (int i = 0; i < 4; i++)
#pragma unroll
                for (int j = 0; j < 8; j++)
                    MMA_F16(acc[i][j][0], acc[i][j][1], acc[i][j][2], acc[i][j][3],
                            a[i][0], a[i][1], a[i][2], a[i][3], b[j][0], b[j][1]);
        }
    };

    issue_loads(0);
    issue_loads(1);
    issue_loads(2);

    const int NKT = DMODEL / 64;   // 16
    for (int kt = 0; kt < NKT; kt++) {
        const int s = kt & 3;
        mbar_wait_parity(smem_u32 + 8 * s, (kt >> 2) & 1);
        __syncthreads();                 // all warps done with compute(kt-1)
        if (kt + 3 < NKT) issue_loads(kt + 3);
        compute(s);
    }

    // epilogue
#pragma unroll
    for (int i = 0; i < 4; i++) {
        const int mrow0 = m0 + wm + i * 16 + g;
        const int mrow1 = mrow0 + 8;
        const int b0i = mrow0 >> 11, s0i = mrow0 & (SEQ - 1);
        const int b1i = mrow1 >> 11, s1i = mrow1 & (SEQ - 1);
#pragma unroll
        for (int j = 0; j < 8; j++) {
            const int ncol = n0 + wn + j * 8 + q * 2;
            const float bi0 = bias[ncol], bi1 = bias[ncol + 1];
            const float c0 = acc[i][j][0] + bi0, c1 = acc[i][j][1] + bi1;
            const float c2 = acc[i][j][2] + bi0, c3 = acc[i][j][3] + bi1;
            if (LAYOUT == 0) {
                float* out = (float*)outv;
                *(float2*)&out[(size_t)mrow0 * DMODEL + ncol] = make_float2(c0, c1);
                *(float2*)&out[(size_t)mrow1 * DMODEL + ncol] = make_float2(c2, c3);
            } else if (LAYOUT == 1) {
                __half* out = (__half*)outv;
                const int h = ncol >> 6, dk = ncol & 63;
                __half2 v0 = __floats2half2_rn(c0, c1);
                __half2 v1 = __floats2half2_rn(c2, c3);
                *(__half2*)&out[(((size_t)(b0i * NHEADS + h) * SEQ + s0i) << 6) + dk] = v0;
                *(__half2*)&out[(((size_t)(b1i * NHEADS + h) * SEQ + s1i) << 6) + dk] = v1;
            } else {
                __half* out = (__half*)outv;
                const int h = ncol >> 6, dk = ncol & 63;
                const size_t base = ((size_t)(b0i * NHEADS + h) * DK + dk) * SEQ;
                out[base + s0i]       = __float2half_rn(c0);
                out[base + SEQ + s0i] = __float2half_rn(c1);
                const size_t base1 = ((size_t)(b1i * NHEADS + h) * DK + dk) * SEQ;
                out[base1 + s1i]       = __float2half_rn(c2);
                out[base1 + SEQ + s1i] = __float2half_rn(c3);
            }
        }
    }
}

__global__ __launch_bounds__(256, 1) void qkv_gemm_f16(
    const float* __restrict__ bq, const float* __restrict__ bk,
    const float* __restrict__ bv)
{
    if (blockIdx.z == 0)      gemm_f16_body<1>(g_xh, g_wqt, bq, g_Qh);
    else if (blockIdx.z == 1) gemm_f16_body<1>(g_xh, g_wkt, bk, g_Kh);
    else                      gemm_f16_body<2>(g_xh, g_wvt, bv, g_Vh);
}

__global__ __launch_bounds__(256, 1) void out_gemm_f16(
    const float* __restrict__ bo, float* __restrict__ out)
{
    gemm_f16_body<0>(g_ctxh, g_wot, bo, out);
}

// ---------------- flash attention, fp16 mma, bulk KV, 3 stages ----------------
#define AST 72
#define AROWB 144
#define AQ_BYTES (128 * AROWB)               // 18432
#define AKV_STAGE (64 * AROWB * 2)           // K + V = 18432
#define ANST 3
#define A_Q_OFF   64
#define A_KV_OFF  (A_Q_OFF + AQ_BYTES)       // 18496
#define A_P_OFF   (A_KV_OFF + ANST * AKV_STAGE)  // 73792
#define A_M_OFF   (A_P_OFF + AQ_BYTES)       // 92224
#define ATT_SMEM  (A_M_OFF + SEQ * 4)        // 100416 B

__global__ __launch_bounds__(256, 2) void flash_attn_f16(const int* __restrict__ mask)
{
    extern __shared__ char sma[];
    const uint32_t smem_u32 = (uint32_t)__cvta_generic_to_shared(sma);
    __half* Qs = (__half*)(sma + A_Q_OFF);
    __half* Ps = (__half*)(sma + A_P_OFF);
    int*    Ms = (int*)(sma + A_M_OFF);

    const int bh = blockIdx.y;
    const int b  = bh >> 4;
    const int h  = bh & 15;
    const int q0 = blockIdx.x * 128;
    const int tid = threadIdx.x;
    const int warp = tid >> 5, lane = tid & 31;
    const int g = lane >> 2, q = lane & 3;
    const int wq0 = warp * 16;

    const __half* Qp = g_Qh + (size_t)bh * SEQ * DK + (size_t)q0 * DK;
    const __half* Kp = g_Kh + (size_t)bh * SEQ * DK;
    const __half* Vp = g_Vh + (size_t)bh * DK * SEQ;   // [dk][S]

    if (tid == 0) {
#pragma unroll
        for (int s = 0; s < ANST; s++) MBARRIER_INIT(smem_u32 + 8 * s, 128);
    }
    __syncthreads();

    // Q tile via cp.async (one-time): 128 rows x 128B
#pragma unroll
    for (int i = 0; i < 4; i++) {
        int id = tid + i * 256;
        int r = id >> 3, c = id & 7;
        cp_async16(smem_u32 + A_Q_OFF + (uint32_t)(r * AROWB + c * 16),
                   Qp + (size_t)r * DK + c * 8);
    }
    CP_COMMIT();
    const int* mbase = mask + b * SEQ;
#pragma unroll
    for (int i = 0; i < 8; i++) Ms[tid + i * 256] = mbase[tid + i * 256];

    auto issue_kv = [&](int kt) {
        const int stage = kt % 3;
        const uint32_t mb = smem_u32 + 8 * stage;
        const uint32_t base = smem_u32 + A_KV_OFF + stage * AKV_STAGE;
        if (tid < 128) {
            MBAR_ARRIVE_TX(mb, 128u);
            if (tid < 64)
                bulk_cp128(base + tid * AROWB,
                           Kp + (size_t)(kt * 64 + tid) * DK, mb);
            else
                bulk_cp128(base + 64 * AROWB + (tid - 64) * AROWB,
                           Vp + (size_t)(tid - 64) * SEQ + kt * 64, mb);
        }
    };

    issue_kv(0);
    issue_kv(1);
    CP_WAIT(0);   // Q resident

    float m0 = -1e30f, m1 = -1e30f, l0 = 0.f, l1 = 0.f;
    float o[8][4];
#pragma unroll
    for (int j = 0; j < 8; j++)
#pragma unroll
        for (int c = 0; c < 4; c++) o[j][c] = 0.f;

    const int NKT = SEQ / 64;   // 32
    for (int kt = 0; kt < NKT; kt++) {
        const int st = kt % 3;
        mbar_wait_parity(smem_u32 + 8 * st, (kt / 3) & 1);
        __syncthreads();             // all warps done with compute(kt-1); Q/mask visible
        if (kt + 2 < NKT) issue_kv(kt + 2);

        const __half* Kt = (__half*)(sma + A_KV_OFF + st * AKV_STAGE);
        const __half* Vt = Kt + 64 * AST;

        // ---- S = Q @ K^T ----
        float s[8][4];
#pragma unroll
        for (int j = 0; j < 8; j++)
#pragma unroll
            for (int c = 0; c < 4; c++) s[j][c] = 0.f;

#pragma unroll
        for (int ks = 0; ks < 4; ks++) {
            const int kc = ks * 16 + 2 * q;
            uint32_t a0 = *(const uint32_t*)&Qs[(wq0 + g) * AST + kc];
            uint32_t a1 = *(const uint32_t*)&Qs[(wq0 + g + 8) * AST + kc];
            uint32_t a2 = *(const uint32_t*)&Qs[(wq0 + g) * AST + kc + 8];
            uint32_t a3 = *(const uint32_t*)&Qs[(wq0 + g + 8) * AST + kc + 8];
#pragma unroll
            for (int nt = 0; nt < 8; nt++) {
                uint32_t b0 = *(const uint32_t*)&Kt[(nt * 8 + g) * AST + kc];
                uint32_t b1 = *(const uint32_t*)&Kt[(nt * 8 + g) * AST + kc + 8];
                MMA_F16(s[nt][0], s[nt][1], s[nt][2], s[nt][3],
                        a0, a1, a2, a3, b0, b1);
            }
        }

        // ---- mask + scale ----
        const int kbase = kt * 64;
#pragma unroll
        for (int nt = 0; nt < 8; nt++) {
            const int mv0 = Ms[kbase + nt * 8 + 2 * q];
            const int mv1 = Ms[kbase + nt * 8 + 2 * q + 1];
            s[nt][0] = mv0 ? s[nt][0] * 0.125f : -1e9f;
            s[nt][1] = mv1 ? s[nt][1] * 0.125f : -1e9f;
            s[nt][2] = mv0 ? s[nt][2] * 0.125f : -1e9f;
            s[nt][3] = mv1 ? s[nt][3] * 0.125f : -1e9f;
        }

        // ---- online softmax ----
        float mt0 = s[0][0], mt1 = s[0][2];
#pragma unroll
        for (int nt = 0; nt < 8; nt++) {
            mt0 = fmaxf(mt0, fmaxf(s[nt][0], s[nt][1]));
            mt1 = fmaxf(mt1, fmaxf(s[nt][2], s[nt][3]));
        }
        mt0 = fmaxf(mt0, __shfl_xor_sync(0xffffffffu, mt0, 1));
        mt0 = fmaxf(mt0, __shfl_xor_sync(0xffffffffu, mt0, 2));
        mt1 = fmaxf(mt1, __shfl_xor_sync(0xffffffffu, mt1, 1));
        mt1 = fmaxf(mt1, __shfl_xor_sync(0xffffffffu, mt1, 2));

        const float nm0 = fmaxf(m0, mt0);
        const float nm1 = fmaxf(m1, mt1);
        const float al0 = __expf(m0 - nm0);
        const float al1 = __expf(m1 - nm1);
        m0 = nm0; m1 = nm1;

        float ls0 = 0.f, ls1 = 0.f;
#pragma unroll
        for (int nt = 0; nt < 8; nt++) {
            float p00 = __expf(s[nt][0] - nm0);
            float p01 = __expf(s[nt][1] - nm0);
            float p10 = __expf(s[nt][2] - nm1);
            float p11 = __expf(s[nt][3] - nm1);
            ls0 += p00 + p01;
            ls1 += p10 + p11;
            __half2 h0 = __floats2half2_rn(p00, p01);
            __half2 h1 = __floats2half2_rn(p10, p11);
            *(__half2*)&Ps[(wq0 + g) * AST + nt * 8 + 2 * q] = h0;
            *(__half2*)&Ps[(wq0 + g + 8) * AST + nt * 8 + 2 * q] = h1;
        }
        ls0 += __shfl_xor_sync(0xffffffffu, ls0, 1);
        ls0 += __shfl_xor_sync(0xffffffffu, ls0, 2);
        ls1 += __shfl_xor_sync(0xffffffffu, ls1, 1);
        ls1 += __shfl_xor_sync(0xffffffffu, ls1, 2);
        l0 = l0 * al0 + ls0;
        l1 = l1 * al1 + ls1;

#pragma unroll
        for (int nt = 0; nt < 8; nt++) {
            o[nt][0] *= al0; o[nt][1] *= al0;
            o[nt][2] *= al1; o[nt][3] *= al1;
        }

        __syncwarp();   // Ps rows are warp-private

        // ---- O += P @ V ----
#pragma unroll
        for (int ks = 0; ks < 4; ks++) {
            const int kc = ks * 16 + 2 * q;
            uint32_t a0 = *(const uint32_t*)&Ps[(wq0 + g) * AST + kc];
            uint32_t a1 = *(const uint32_t*)&Ps[(wq0 + g + 8) * AST + kc];
            uint32_t a2 = *(const uint32_t*)&Ps[(wq0 + g) * AST + kc + 8];
            uint32_t a3 = *(const uint32_t*)&Ps[(wq0 + g + 8) * AST + kc + 8];
#pragma unroll
            for (int nt = 0; nt < 8; nt++) {
                uint32_t b0 = *(const uint32_t*)&Vt[(nt * 8 + g) * AST + kc];
                uint32_t b1 = *(const uint32_t*)&Vt[(nt * 8 + g) * AST + kc + 8];
                MMA_F16(o[nt][0], o[nt][1], o[nt][2], o[nt][3],
                        a0, a1, a2, a3, b0, b1);
            }
        }
    }

    // ---- epilogue ----
    const float inv0 = 1.f / l0;
    const float inv1 = 1.f / l1;
    const int row0 = q0 + wq0 + g;
    const int row1 = row0 + 8;
    __half* out0 = g_ctxh + (size_t)(b * SEQ + row0) * DMODEL + h * 64;
    __half* out1 = g_ctxh + (size_t)(b * SEQ + row1) * DMODEL + h * 64;
#pragma unroll
    for (int nt = 0; nt < 8; nt++) {
        const int c = nt * 8 + 2 * q;
        __half2 v0 = __floats2half2_rn(o[nt][0] * inv0, o[nt][1] * inv0);
        __half2 v1 = __floats2half2_rn(o[nt][2] * inv1, o[nt][3] * inv1);
        *(__half2*)&out0[c] = v0;
        *(__half2*)&out1[c] = v1;
    }
}

// ---------------- launch ------------------------------------------------------
extern "C" void kernel_launch(void* const* d_in, const int* in_sizes, int n_in,
                              void* d_out, int out_size)
{
    const float* x  = (const float*)d_in[0];
    const int* mask = (const int*)d_in[1];
    const float* wq = (const float*)d_in[2];
    const float* bq = (const float*)d_in[3];
    const float* wk = (const float*)d_in[4];
    const float* bk = (const float*)d_in[5];
    const float* wv = (const float*)d_in[6];
    const float* bv = (const float*)d_in[7];
    const float* wo = (const float*)d_in[8];
    const float* bo = (const float*)d_in[9];

    __half* d_xh;   cudaGetSymbolAddress((void**)&d_xh, g_xh);
    __half* d_wqt;  cudaGetSymbolAddress((void**)&d_wqt, g_wqt);
    __half* d_wkt;  cudaGetSymbolAddress((void**)&d_wkt, g_wkt);
    __half* d_wvt;  cudaGetSymbolAddress((void**)&d_wvt, g_wvt);
    __half* d_wot;  cudaGetSymbolAddress((void**)&d_wot, g_wot);

    const int nx4 = BATCH * SEQ * DMODEL / 4;
    cvt_f16_kernel<<<(nx4 + 255) / 256, 256>>>(x, d_xh, nx4);
    dim3 tg(DMODEL / 32, DMODEL / 32, 4);
    cvt_transpose4_kernel<<<tg, 256>>>(wq, wk, wv, wo, d_wqt, d_wkt, d_wvt, d_wot);

    // 1) QKV projections (one launch, z = Q/K/V)
    cudaFuncSetAttribute(qkv_gemm_f16,
                         cudaFuncAttributeMaxDynamicSharedMemorySize, GSMEM);
    dim3 g1(DMODEL / 256, (BATCH * SEQ) / 128, 3);
    qkv_gemm_f16<<<g1, 256, GSMEM>>>(bq, bk, bv);

    // 2) flash attention
    cudaFuncSetAttribute(flash_attn_f16,
                         cudaFuncAttributeMaxDynamicSharedMemorySize, ATT_SMEM);
    flash_attn_f16<<<dim3(SEQ / 128, BATCH * NHEADS), 256, ATT_SMEM>>>(mask);

    // 3) output projection
    cudaFuncSetAttribute(out_gemm_f16,
                         cudaFuncAttributeMaxDynamicSharedMemorySize, GSMEM);
    dim3 g3(DMODEL / 256, (BATCH * SEQ) / 128);
    out_gemm_f16<<<g3, 256, GSMEM>>>(bo, (float*)d_out);
}

// round 10
// speedup vs baseline: 1.3558x; 1.3558x over previous
#include <cuda_runtime.h>
#include <cuda_fp16.h>
#include <cstdint>

#define BATCH 4
#define SEQ   2048
#define DMODEL 1024
#define NHEADS 16
#define DK    64

// ---------------- scratch (static device globals; no allocation) ------------
__device__ __half g_Qh[BATCH * NHEADS * SEQ * DK];    // [B,H,S,Dk] fp16 (pre-scaled by 0.125)
__device__ __half g_Kh[BATCH * NHEADS * SEQ * DK];    // [B,H,S,Dk] fp16
__device__ __half g_Vh[BATCH * NHEADS * DK * SEQ];    // [B,H,Dk,S] fp16 (transposed)
__device__ __half g_ctxh[BATCH * SEQ * DMODEL];       // [B,S,D] fp16
__device__ __half g_xh[BATCH * SEQ * DMODEL];         // x fp16
__device__ __half g_wqt[DMODEL * DMODEL];             // [N,K] fp16 (transposed)
__device__ __half g_wkt[DMODEL * DMODEL];
__device__ __half g_wvt[DMODEL * DMODEL];
__device__ __half g_wot[DMODEL * DMODEL];

// ---------------- helpers ----------------------------------------------------
__device__ __forceinline__ void cp_async16(uint32_t smem, const void* gmem) {
    asm volatile("cp.async.ca.shared.global [%0], [%1], 16;\n"
                 :: "r"(smem), "l"(gmem));
}
#define CP_COMMIT()  asm volatile("cp.async.commit_group;\n" ::)
#define CP_WAIT(n)   asm volatile("cp.async.wait_group %0;\n" :: "n"(n))

#define MMA_F16(d0,d1,d2,d3,a0,a1,a2,a3,b0,b1)                                  \
    asm volatile(                                                               \
        "mma.sync.aligned.m16n8k16.row.col.f32.f16.f16.f32 "                    \
        "{%0,%1,%2,%3}, {%4,%5,%6,%7}, {%8,%9}, {%0,%1,%2,%3};\n"               \
        : "+f"(d0), "+f"(d1), "+f"(d2), "+f"(d3)                                \
        : "r"(a0), "r"(a1), "r"(a2), "r"(a3), "r"(b0), "r"(b1))

// ---------------- prep kernels -----------------------------------------------
__global__ void cvt_f16_kernel(const float* __restrict__ src,
                               __half* __restrict__ dst, int n4)
{
    int i = blockIdx.x * blockDim.x + threadIdx.x;
    if (i < n4) {
        float4 v = ((const float4*)src)[i];
        __half2 h0 = __floats2half2_rn(v.x, v.y);
        __half2 h1 = __floats2half2_rn(v.z, v.w);
        uint2 u;
        u.x = *(uint32_t*)&h0;
        u.y = *(uint32_t*)&h1;
        ((uint2*)dst)[i] = u;
    }
}

// 4 weights [K,N] f32 -> [N,K] f16, z selects the matrix
__global__ void cvt_transpose4_kernel(
    const float* __restrict__ w0, const float* __restrict__ w1,
    const float* __restrict__ w2, const float* __restrict__ w3,
    __half* __restrict__ d0, __half* __restrict__ d1,
    __half* __restrict__ d2, __half* __restrict__ d3)
{
    const float* src;
    __half* dst;
    switch (blockIdx.z) {
        case 0: src = w0; dst = d0; break;
        case 1: src = w1; dst = d1; break;
        case 2: src = w2; dst = d2; break;
        default: src = w3; dst = d3; break;
    }
    __shared__ float t[32][33];
    const int bx = blockIdx.x * 32;   // n
    const int by = blockIdx.y * 32;   // k
    const int tx = threadIdx.x & 31, ty = threadIdx.x >> 5;
#pragma unroll
    for (int i = 0; i < 4; i++)
        t[ty + i * 8][tx] = src[(size_t)(by + ty + i * 8) * DMODEL + bx + tx];
    __syncthreads();
#pragma unroll
    for (int i = 0; i < 4; i++)
        dst[(size_t)(bx + ty + i * 8) * DMODEL + by + tx] =
            __float2half_rn(t[tx][ty + i * 8]);
}

// ---------------- fp16 mma GEMM (round-8 proven form) -------------------------
// C[8192,1024] = X[8192,1024] @ Wt[1024,1024]^T + bias, optional output scale.
// CTA tile 128x256, k-block 64. 8 warps (2m x 4n), warp tile 64x64.
#define GST 72
#define GA_H  (128 * GST)              // 9216 halves per A stage
#define GB_H  (256 * GST)              // 18432 halves per B stage
#define GSMEM ((2 * GA_H + 2 * GB_H) * 2)   // 110592 bytes

// LAYOUT 0: fp32 out.  LAYOUT 1: Q/K fp16 scatter [B,H,S,dk].
// LAYOUT 2: V fp16 transposed scatter [B,H,dk,S].
template <int LAYOUT>
__device__ __forceinline__ void gemm_f16_body(
    const __half* __restrict__ X, const __half* __restrict__ Wt,
    const float* __restrict__ bias, void* __restrict__ outv, float oscale)
{
    extern __shared__ __half gsmh[];
    const uint32_t smem_u32 = (uint32_t)__cvta_generic_to_shared(gsmh);

    const int tid = threadIdx.x;
    const int m0 = blockIdx.y * 128;
    const int n0 = blockIdx.x * 256;
    const int warp = tid >> 5, lane = tid & 31;
    const int g = lane >> 2, q = lane & 3;
    const int wm = (warp >> 2) * 64;
    const int wn = (warp & 3) * 64;

    float acc[4][8][4];
#pragma unroll
    for (int i = 0; i < 4; i++)
#pragma unroll
        for (int j = 0; j < 8; j++)
#pragma unroll
            for (int c = 0; c < 4; c++) acc[i][j][c] = 0.f;

    auto load_chunk = [&](int kt, int stage) {
        const __half* Xp = X + (size_t)m0 * DMODEL + kt * 64;
        const uint32_t ab = smem_u32 + stage * (GA_H * 2);
#pragma unroll
        for (int i = 0; i < 4; i++) {
            int id = tid + i * 256;
            int r = id >> 3, c = id & 7;
            cp_async16(ab + (uint32_t)(r * (GST * 2) + c * 16),
                       Xp + (size_t)r * DMODEL + c * 8);
        }
        const __half* Bp = Wt + (size_t)n0 * DMODEL + kt * 64;
        const uint32_t bb = smem_u32 + 2 * GA_H * 2 + stage * (GB_H * 2);
#pragma unroll
        for (int i = 0; i < 8; i++) {
            int id = tid + i * 256;
            int r = id >> 3, c = id & 7;
            cp_async16(bb + (uint32_t)(r * (GST * 2) + c * 16),
                       Bp + (size_t)r * DMODEL + c * 8);
        }
    };

    auto compute = [&](int stage) {
        const __half* Xs = gsmh + stage * GA_H;
        const __half* Ws = gsmh + 2 * GA_H + stage * GB_H;
#pragma unroll
        for (int ks = 0; ks < 4; ks++) {
            const int kc = ks * 16 + 2 * q;
            uint32_t a[4][4], b[8][2];
#pragma unroll
            for (int i = 0; i < 4; i++) {
                const int row = wm + i * 16 + g;
                a[i][0] = *(const uint32_t*)&Xs[row * GST + kc];
                a[i][1] = *(const uint32_t*)&Xs[(row + 8) * GST + kc];
                a[i][2] = *(const uint32_t*)&Xs[row * GST + kc + 8];
                a[i][3] = *(const uint32_t*)&Xs[(row + 8) * GST + kc + 8];
            }
#pragma unroll
            for (int j = 0; j < 8; j++) {
                const int col = wn + j * 8 + g;
                b[j][0] = *(const uint32_t*)&Ws[col * GST + kc];
                b[j][1] = *(const uint32_t*)&Ws[col * GST + kc + 8];
            }
#pragma unroll
            for (int i = 0; i < 4; i++)
#pragma unroll
                for (int j = 0; j < 8; j++)
                    MMA_F16(acc[i][j][0], acc[i][j][1], acc[i][j][2], acc[i][j][3],
                            a[i][0], a[i][1], a[i][2], a[i][3], b[j][0], b[j][1]);
        }
    };

    load_chunk(0, 0);
    CP_COMMIT();

    const int NKT = DMODEL / 64;   // 16
    for (int kt = 0; kt < NKT; kt++) {
        const int cur = kt & 1;
        if (kt < NKT - 1) {
            load_chunk(kt + 1, cur ^ 1);
            CP_COMMIT();
            CP_WAIT(1);
        } else {
            CP_WAIT(0);
        }
        __syncthreads();
        compute(cur);
        __syncthreads();
    }

    // epilogue
#pragma unroll
    for (int i = 0; i < 4; i++) {
        const int mrow0 = m0 + wm + i * 16 + g;
        const int mrow1 = mrow0 + 8;
        const int b0i = mrow0 >> 11, s0i = mrow0 & (SEQ - 1);
        const int b1i = mrow1 >> 11, s1i = mrow1 & (SEQ - 1);
#pragma unroll
        for (int j = 0; j < 8; j++) {
            const int ncol = n0 + wn + j * 8 + q * 2;
            const float bi0 = bias[ncol], bi1 = bias[ncol + 1];
            const float c0 = (acc[i][j][0] + bi0) * oscale;
            const float c1 = (acc[i][j][1] + bi1) * oscale;
            const float c2 = (acc[i][j][2] + bi0) * oscale;
            const float c3 = (acc[i][j][3] + bi1) * oscale;
            if (LAYOUT == 0) {
                float* out = (float*)outv;
                *(float2*)&out[(size_t)mrow0 * DMODEL + ncol] = make_float2(c0, c1);
                *(float2*)&out[(size_t)mrow1 * DMODEL + ncol] = make_float2(c2, c3);
            } else if (LAYOUT == 1) {
                __half* out = (__half*)outv;
                const int h = ncol >> 6, dk = ncol & 63;
                __half2 v0 = __floats2half2_rn(c0, c1);
                __half2 v1 = __floats2half2_rn(c2, c3);
                *(__half2*)&out[(((size_t)(b0i * NHEADS + h) * SEQ + s0i) << 6) + dk] = v0;
                *(__half2*)&out[(((size_t)(b1i * NHEADS + h) * SEQ + s1i) << 6) + dk] = v1;
            } else {
                __half* out = (__half*)outv;
                const int h = ncol >> 6, dk = ncol & 63;
                const size_t base = ((size_t)(b0i * NHEADS + h) * DK + dk) * SEQ;
                out[base + s0i]       = __float2half_rn(c0);
                out[base + SEQ + s0i] = __float2half_rn(c1);
                const size_t base1 = ((size_t)(b1i * NHEADS + h) * DK + dk) * SEQ;
                out[base1 + s1i]       = __float2half_rn(c2);
                out[base1 + SEQ + s1i] = __float2half_rn(c3);
            }
        }
    }
}

__global__ __launch_bounds__(256, 1) void qkv_gemm_f16(
    const float* __restrict__ bq, const float* __restrict__ bk,
    const float* __restrict__ bv)
{
    if (blockIdx.z == 0)      gemm_f16_body<1>(g_xh, g_wqt, bq, g_Qh, 0.125f);
    else if (blockIdx.z == 1) gemm_f16_body<1>(g_xh, g_wkt, bk, g_Kh, 1.0f);
    else                      gemm_f16_body<2>(g_xh, g_wvt, bv, g_Vh, 1.0f);
}

__global__ __launch_bounds__(256, 1) void out_gemm_f16(
    const float* __restrict__ bo, float* __restrict__ out)
{
    gemm_f16_body<0>(g_ctxh, g_wot, bo, out, 1.0f);
}

// ---------------- flash attention, fp16 mma, P in registers ------------------
// CTA: 128 queries, key tiles of 64, 8 warps x 16 q-rows, 3-stage KV cp.async.
#define AST 72
#define AQ_H (128 * AST)            // 9216 halves
#define AKV_H (2 * 64 * AST)        // K+V per stage = 9216 halves
#define ANST 3
// halves: Q + 3*(K+V) = 9216 + 27648 = 36864 -> 73728 B, + mask 8192
#define ATT_SMEM (36864 * 2 + SEQ * 4)   // 81920 B

__global__ __launch_bounds__(256, 2) void flash_attn_f16(const int* __restrict__ mask)
{
    extern __shared__ __half smh[];
    __half* Qs = smh;                       // 128 x 72
    __half* KVs = smh + AQ_H;               // 3 stages x (64x72 K + 64x72 V)
    int*    Ms = (int*)(smh + AQ_H + ANST * AKV_H);

    const uint32_t smem_u32 = (uint32_t)__cvta_generic_to_shared(smh);
    const uint32_t Qs_u = smem_u32;
    const uint32_t KV_u = smem_u32 + AQ_H * 2;

    const int bh = blockIdx.y;
    const int b  = bh >> 4;
    const int h  = bh & 15;
    const int q0 = blockIdx.x * 128;
    const int tid = threadIdx.x;
    const int warp = tid >> 5, lane = tid & 31;
    const int g = lane >> 2, q = lane & 3;
    const int wq0 = warp * 16;

    const __half* Qp = g_Qh + (size_t)bh * SEQ * DK + (size_t)q0 * DK;
    const __half* Kp = g_Kh + (size_t)bh * SEQ * DK;
    const __half* Vp = g_Vh + (size_t)bh * DK * SEQ;   // [dk][S]

    // Q tile: 128 rows x 128B = 1024 cp16 (group 0... folded into stage waits)
#pragma unroll
    for (int i = 0; i < 4; i++) {
        int id = tid + i * 256;
        int r = id >> 3, c = id & 7;
        cp_async16(Qs_u + (uint32_t)(r * (AST * 2) + c * 16),
                   Qp + (size_t)r * DK + c * 8);
    }
    const int* mbase = mask + b * SEQ;
#pragma unroll
    for (int i = 0; i < 8; i++) Ms[tid + i * 256] = mbase[tid + i * 256];

    auto issue_kv = [&](int kt) {
        const int stage = kt % 3;
        const __half* Kpt = Kp + (size_t)kt * 64 * DK;
        const __half* Vpt = Vp + (size_t)kt * 64;
        const uint32_t kb = KV_u + stage * (AKV_H * 2);
        const uint32_t vb = kb + 64 * AST * 2;
#pragma unroll
        for (int i = 0; i < 2; i++) {     // K: 512 cp16
            int id = tid + i * 256;
            int r = id >> 3, c = id & 7;
            cp_async16(kb + (uint32_t)(r * (AST * 2) + c * 16),
                       Kpt + (size_t)r * DK + c * 8);
        }
#pragma unroll
        for (int i = 0; i < 2; i++) {     // V: 512 cp16 ([dk] rows, stride SEQ)
            int id = tid + i * 256;
            int r = id >> 3, c = id & 7;
            cp_async16(vb + (uint32_t)(r * (AST * 2) + c * 16),
                       Vpt + (size_t)r * SEQ + c * 8);
        }
    };

    // groups: {Q+kv0}, {kv1}, {kv2}
    issue_kv(0); CP_COMMIT();
    issue_kv(1); CP_COMMIT();
    issue_kv(2); CP_COMMIT();

    float m0 = -1e30f, m1 = -1e30f, l0 = 0.f, l1 = 0.f;
    float o[8][4];
#pragma unroll
    for (int j = 0; j < 8; j++)
#pragma unroll
        for (int c = 0; c < 4; c++) o[j][c] = 0.f;

    const int NKT = SEQ / 64;   // 32
    for (int kt = 0; kt < NKT; kt++) {
        if (kt < NKT - 2)      CP_WAIT(2);
        else if (kt < NKT - 1) CP_WAIT(1);
        else                   CP_WAIT(0);
        __syncthreads();

        const __half* Kt = KVs + (kt % 3) * AKV_H;
        const __half* Vt = Kt + 64 * AST;

        // ---- S = Q @ K^T  (Q pre-scaled by 0.125) ----
        float s[8][4];
#pragma unroll
        for (int j = 0; j < 8; j++)
#pragma unroll
            for (int c = 0; c < 4; c++) s[j][c] = 0.f;

#pragma unroll
        for (int ks = 0; ks < 4; ks++) {
            const int kc = ks * 16 + 2 * q;
            uint32_t a0 = *(const uint32_t*)&Qs[(wq0 + g) * AST + kc];
            uint32_t a1 = *(const uint32_t*)&Qs[(wq0 + g + 8) * AST + kc];
            uint32_t a2 = *(const uint32_t*)&Qs[(wq0 + g) * AST + kc + 8];
            uint32_t a3 = *(const uint32_t*)&Qs[(wq0 + g + 8) * AST + kc + 8];
#pragma unroll
            for (int nt = 0; nt < 8; nt++) {
                uint32_t b0 = *(const uint32_t*)&Kt[(nt * 8 + g) * AST + kc];
                uint32_t b1 = *(const uint32_t*)&Kt[(nt * 8 + g) * AST + kc + 8];
                MMA_F16(s[nt][0], s[nt][1], s[nt][2], s[nt][3],
                        a0, a1, a2, a3, b0, b1);
            }
        }

        // ---- mask (scale already folded into Q) ----
        const int kbase = kt * 64;
#pragma unroll
        for (int nt = 0; nt < 8; nt++) {
            const int mv0 = Ms[kbase + nt * 8 + 2 * q];
            const int mv1 = Ms[kbase + nt * 8 + 2 * q + 1];
            if (mv0 == 0) { s[nt][0] = -1e9f; s[nt][2] = -1e9f; }
            if (mv1 == 0) { s[nt][1] = -1e9f; s[nt][3] = -1e9f; }
        }

        // ---- online softmax (rows wq0+g, wq0+g+8) ----
        float mt0 = s[0][0], mt1 = s[0][2];
#pragma unroll
        for (int nt = 0; nt < 8; nt++) {
            mt0 = fmaxf(mt0, fmaxf(s[nt][0], s[nt][1]));
            mt1 = fmaxf(mt1, fmaxf(s[nt][2], s[nt][3]));
        }
        mt0 = fmaxf(mt0, __shfl_xor_sync(0xffffffffu, mt0, 1));
        mt0 = fmaxf(mt0, __shfl_xor_sync(0xffffffffu, mt0, 2));
        mt1 = fmaxf(mt1, __shfl_xor_sync(0xffffffffu, mt1, 1));
        mt1 = fmaxf(mt1, __shfl_xor_sync(0xffffffffu, mt1, 2));

        const float nm0 = fmaxf(m0, mt0);
        const float nm1 = fmaxf(m1, mt1);
        const float al0 = __expf(m0 - nm0);
        const float al1 = __expf(m1 - nm1);
        m0 = nm0; m1 = nm1;

        // ---- P in registers, packed directly as PV A-fragments ----
        uint32_t P2[8][2];
        float ls0 = 0.f, ls1 = 0.f;
#pragma unroll
        for (int nt = 0; nt < 8; nt++) {
            float p00 = __expf(s[nt][0] - nm0);
            float p01 = __expf(s[nt][1] - nm0);
            float p10 = __expf(s[nt][2] - nm1);
            float p11 = __expf(s[nt][3] - nm1);
            ls0 += p00 + p01;
            ls1 += p10 + p11;
            __half2 hh0 = __floats2half2_rn(p00, p01);
            __half2 hh1 = __floats2half2_rn(p10, p11);
            P2[nt][0] = *(uint32_t*)&hh0;
            P2[nt][1] = *(uint32_t*)&hh1;
        }
        ls0 += __shfl_xor_sync(0xffffffffu, ls0, 1);
        ls0 += __shfl_xor_sync(0xffffffffu, ls0, 2);
        ls1 += __shfl_xor_sync(0xffffffffu, ls1, 1);
        ls1 += __shfl_xor_sync(0xffffffffu, ls1, 2);
        l0 = l0 * al0 + ls0;
        l1 = l1 * al1 + ls1;

#pragma unroll
        for (int nt = 0; nt < 8; nt++) {
            o[nt][0] *= al0; o[nt][1] *= al0;
            o[nt][2] *= al1; o[nt][3] *= al1;
        }

        // ---- O += P @ V  (A from registers: C-fragment == A-fragment identity) ----
#pragma unroll
        for (int ks = 0; ks < 4; ks++) {
            const int kc = ks * 16 + 2 * q;
            const uint32_t a0 = P2[2 * ks][0];
            const uint32_t a1 = P2[2 * ks][1];
            const uint32_t a2 = P2[2 * ks + 1][0];
            const uint32_t a3 = P2[2 * ks + 1][1];
#pragma unroll
            for (int nt = 0; nt < 8; nt++) {
                uint32_t b0 = *(const uint32_t*)&Vt[(nt * 8 + g) * AST + kc];
                uint32_t b1 = *(const uint32_t*)&Vt[(nt * 8 + g) * AST + kc + 8];
                MMA_F16(o[nt][0], o[nt][1], o[nt][2], o[nt][3],
                        a0, a1, a2, a3, b0, b1);
            }
        }

        __syncthreads();   // stage fully consumed before refill

        if (kt + 3 < NKT) {
            issue_kv(kt + 3);
            CP_COMMIT();
        }
    }

    // ---- epilogue: normalize, write ctx fp16 [B,S,D] ----
    const float inv0 = 1.f / l0;
    const float inv1 = 1.f / l1;
    const int row0 = q0 + wq0 + g;
    const int row1 = row0 + 8;
    __half* out0 = g_ctxh + (size_t)(b * SEQ + row0) * DMODEL + h * 64;
    __half* out1 = g_ctxh + (size_t)(b * SEQ + row1) * DMODEL + h * 64;
#pragma unroll
    for (int nt = 0; nt < 8; nt++) {
        const int c = nt * 8 + 2 * q;
        __half2 v0 = __floats2half2_rn(o[nt][0] * inv0, o[nt][1] * inv0);
        __half2 v1 = __floats2half2_rn(o[nt][2] * inv1, o[nt][3] * inv1);
        *(__half2*)&out0[c] = v0;
        *(__half2*)&out1[c] = v1;
    }
}

// ---------------- launch ------------------------------------------------------
extern "C" void kernel_launch(void* const* d_in, const int* in_sizes, int n_in,
                              void* d_out, int out_size)
{
    const float* x  = (const float*)d_in[0];
    const int* mask = (const int*)d_in[1];
    const float* wq = (const float*)d_in[2];
    const float* bq = (const float*)d_in[3];
    const float* wk = (const float*)d_in[4];
    const float* bk = (const float*)d_in[5];
    const float* wv = (const float*)d_in[6];
    const float* bv = (const float*)d_in[7];
    const float* wo = (const float*)d_in[8];
    const float* bo = (const float*)d_in[9];

    __half* d_xh;   cudaGetSymbolAddress((void**)&d_xh, g_xh);
    __half* d_wqt;  cudaGetSymbolAddress((void**)&d_wqt, g_wqt);
    __half* d_wkt;  cudaGetSymbolAddress((void**)&d_wkt, g_wkt);
    __half* d_wvt;  cudaGetSymbolAddress((void**)&d_wvt, g_wvt);
    __half* d_wot;  cudaGetSymbolAddress((void**)&d_wot, g_wot);

    const int nx4 = BATCH * SEQ * DMODEL / 4;
    cvt_f16_kernel<<<(nx4 + 255) / 256, 256>>>(x, d_xh, nx4);
    dim3 tg(DMODEL / 32, DMODEL / 32, 4);
    cvt_transpose4_kernel<<<tg, 256>>>(wq, wk, wv, wo, d_wqt, d_wkt, d_wvt, d_wot);

    // 1) QKV projections (Q epilogue folds 1/sqrt(dk))
    cudaFuncSetAttribute(qkv_gemm_f16,
                         cudaFuncAttributeMaxDynamicSharedMemorySize, GSMEM);
    dim3 g1(DMODEL / 256, (BATCH * SEQ) / 128, 3);
    qkv_gemm_f16<<<g1, 256, GSMEM>>>(bq, bk, bv);

    // 2) flash attention (P in registers)
    cudaFuncSetAttribute(flash_attn_f16,
                         cudaFuncAttributeMaxDynamicSharedMemorySize, ATT_SMEM);
    flash_attn_f16<<<dim3(SEQ / 128, BATCH * NHEADS), 256, ATT_SMEM>>>(mask);

    // 3) output projection
    cudaFuncSetAttribute(out_gemm_f16,
                         cudaFuncAttributeMaxDynamicSharedMemorySize, GSMEM);
    dim3 g3(DMODEL / 256, (BATCH * SEQ) / 128);
    out_gemm_f16<<<g3, 256, GSMEM>>>(bo, (float*)d_out);
}

// round 11
// speedup vs baseline: 1.4282x; 1.0535x over previous
#include <cuda_runtime.h>
#include <cuda_fp16.h>
#include <cstdint>

#define BATCH 4
#define SEQ   2048
#define DMODEL 1024
#define NHEADS 16
#define DK    64

// ---------------- scratch (static device globals; no allocation) ------------
__device__ __half g_Qh[BATCH * NHEADS * SEQ * DK];    // [B,H,S,Dk] fp16 (pre-scaled by 0.125*log2e)
__device__ __half g_Kh[BATCH * NHEADS * SEQ * DK];    // [B,H,S,Dk] fp16
__device__ __half g_Vh[BATCH * NHEADS * DK * SEQ];    // [B,H,Dk,S] fp16 (transposed)
__device__ __half g_ctxh[BATCH * SEQ * DMODEL];       // [B,S,D] fp16
__device__ __half g_xh[BATCH * SEQ * DMODEL];         // x fp16
__device__ __half g_wqt[DMODEL * DMODEL];             // [N,K] fp16 (transposed)
__device__ __half g_wkt[DMODEL * DMODEL];
__device__ __half g_wvt[DMODEL * DMODEL];
__device__ __half g_wot[DMODEL * DMODEL];

// ---------------- helpers ----------------------------------------------------
__device__ __forceinline__ void cp_async16(uint32_t smem, const void* gmem) {
    asm volatile("cp.async.ca.shared.global [%0], [%1], 16;\n"
                 :: "r"(smem), "l"(gmem));
}
#define CP_COMMIT()  asm volatile("cp.async.commit_group;\n" ::)
#define CP_WAIT(n)   asm volatile("cp.async.wait_group %0;\n" :: "n"(n))

#define MMA_F16(d0,d1,d2,d3,a0,a1,a2,a3,b0,b1)                                  \
    asm volatile(                                                               \
        "mma.sync.aligned.m16n8k16.row.col.f32.f16.f16.f32 "                    \
        "{%0,%1,%2,%3}, {%4,%5,%6,%7}, {%8,%9}, {%0,%1,%2,%3};\n"               \
        : "+f"(d0), "+f"(d1), "+f"(d2), "+f"(d3)                                \
        : "r"(a0), "r"(a1), "r"(a2), "r"(a3), "r"(b0), "r"(b1))

#define LDSM_X4(r0,r1,r2,r3,addr)                                               \
    asm volatile("ldmatrix.sync.aligned.m8n8.x4.shared.b16 {%0,%1,%2,%3}, [%4];"\
        : "=r"(r0), "=r"(r1), "=r"(r2), "=r"(r3) : "r"(addr))

__device__ __forceinline__ float ex2f(float x) {
    float r;
    asm("ex2.approx.f32 %0, %1;" : "=f"(r) : "f"(x));
    return r;
}

#define LOG2E 1.44269504088896f

// ---------------- prep kernels -----------------------------------------------
__global__ void cvt_f16_kernel(const float* __restrict__ src,
                               __half* __restrict__ dst, int n4)
{
    int i = blockIdx.x * blockDim.x + threadIdx.x;
    if (i < n4) {
        float4 v = ((const float4*)src)[i];
        __half2 h0 = __floats2half2_rn(v.x, v.y);
        __half2 h1 = __floats2half2_rn(v.z, v.w);
        uint2 u;
        u.x = *(uint32_t*)&h0;
        u.y = *(uint32_t*)&h1;
        ((uint2*)dst)[i] = u;
    }
}

// 4 weights [K,N] f32 -> [N,K] f16, z selects the matrix
__global__ void cvt_transpose4_kernel(
    const float* __restrict__ w0, const float* __restrict__ w1,
    const float* __restrict__ w2, const float* __restrict__ w3,
    __half* __restrict__ d0, __half* __restrict__ d1,
    __half* __restrict__ d2, __half* __restrict__ d3)
{
    const float* src;
    __half* dst;
    switch (blockIdx.z) {
        case 0: src = w0; dst = d0; break;
        case 1: src = w1; dst = d1; break;
        case 2: src = w2; dst = d2; break;
        default: src = w3; dst = d3; break;
    }
    __shared__ float t[32][33];
    const int bx = blockIdx.x * 32;   // n
    const int by = blockIdx.y * 32;   // k
    const int tx = threadIdx.x & 31, ty = threadIdx.x >> 5;
#pragma unroll
    for (int i = 0; i < 4; i++)
        t[ty + i * 8][tx] = src[(size_t)(by + ty + i * 8) * DMODEL + bx + tx];
    __syncthreads();
#pragma unroll
    for (int i = 0; i < 4; i++)
        dst[(size_t)(bx + ty + i * 8) * DMODEL + by + tx] =
            __float2half_rn(t[tx][ty + i * 8]);
}

// ---------------- fp16 mma GEMM (proven form) ---------------------------------
#define GST 72
#define GA_H  (128 * GST)
#define GB_H  (256 * GST)
#define GSMEM ((2 * GA_H + 2 * GB_H) * 2)   // 110592 bytes

// LAYOUT 0: fp32 out.  LAYOUT 1: Q/K fp16 scatter.  LAYOUT 2: V fp16 transposed.
template <int LAYOUT>
__device__ __forceinline__ void gemm_f16_body(
    const __half* __restrict__ X, const __half* __restrict__ Wt,
    const float* __restrict__ bias, void* __restrict__ outv, float oscale)
{
    extern __shared__ __half gsmh[];
    const uint32_t smem_u32 = (uint32_t)__cvta_generic_to_shared(gsmh);

    const int tid = threadIdx.x;
    const int m0 = blockIdx.y * 128;
    const int n0 = blockIdx.x * 256;
    const int warp = tid >> 5, lane = tid & 31;
    const int g = lane >> 2, q = lane & 3;
    const int wm = (warp >> 2) * 64;
    const int wn = (warp & 3) * 64;

    float acc[4][8][4];
#pragma unroll
    for (int i = 0; i < 4; i++)
#pragma unroll
        for (int j = 0; j < 8; j++)
#pragma unroll
            for (int c = 0; c < 4; c++) acc[i][j][c] = 0.f;

    auto load_chunk = [&](int kt, int stage) {
        const __half* Xp = X + (size_t)m0 * DMODEL + kt * 64;
        const uint32_t ab = smem_u32 + stage * (GA_H * 2);
#pragma unroll
        for (int i = 0; i < 4; i++) {
            int id = tid + i * 256;
            int r = id >> 3, c = id & 7;
            cp_async16(ab + (uint32_t)(r * (GST * 2) + c * 16),
                       Xp + (size_t)r * DMODEL + c * 8);
        }
        const __half* Bp = Wt + (size_t)n0 * DMODEL + kt * 64;
        const uint32_t bb = smem_u32 + 2 * GA_H * 2 + stage * (GB_H * 2);
#pragma unroll
        for (int i = 0; i < 8; i++) {
            int id = tid + i * 256;
            int r = id >> 3, c = id & 7;
            cp_async16(bb + (uint32_t)(r * (GST * 2) + c * 16),
                       Bp + (size_t)r * DMODEL + c * 8);
        }
    };

    auto compute = [&](int stage) {
        const __half* Xs = gsmh + stage * GA_H;
        const __half* Ws = gsmh + 2 * GA_H + stage * GB_H;
#pragma unroll
        for (int ks = 0; ks < 4; ks++) {
            const int kc = ks * 16 + 2 * q;
            uint32_t a[4][4], b[8][2];
#pragma unroll
            for (int i = 0; i < 4; i++) {
                const int row = wm + i * 16 + g;
                a[i][0] = *(const uint32_t*)&Xs[row * GST + kc];
                a[i][1] = *(const uint32_t*)&Xs[(row + 8) * GST + kc];
                a[i][2] = *(const uint32_t*)&Xs[row * GST + kc + 8];
                a[i][3] = *(const uint32_t*)&Xs[(row + 8) * GST + kc + 8];
            }
#pragma unroll
            for (int j = 0; j < 8; j++) {
                const int col = wn + j * 8 + g;
                b[j][0] = *(const uint32_t*)&Ws[col * GST + kc];
                b[j][1] = *(const uint32_t*)&Ws[col * GST + kc + 8];
            }
#pragma unroll
            for (int i = 0; i < 4; i++)
#pragma unroll
                for (int j = 0; j < 8; j++)
                    MMA_F16(acc[i][j][0], acc[i][j][1], acc[i][j][2], acc[i][j][3],
                            a[i][0], a[i][1], a[i][2], a[i][3], b[j][0], b[j][1]);
        }
    };

    load_chunk(0, 0);
    CP_COMMIT();

    const int NKT = DMODEL / 64;   // 16
    for (int kt = 0; kt < NKT; kt++) {
        const int cur = kt & 1;
        if (kt < NKT - 1) {
            load_chunk(kt + 1, cur ^ 1);
            CP_COMMIT();
            CP_WAIT(1);
        } else {
            CP_WAIT(0);
        }
        __syncthreads();
        compute(cur);
        __syncthreads();
    }

    // epilogue
#pragma unroll
    for (int i = 0; i < 4; i++) {
        const int mrow0 = m0 + wm + i * 16 + g;
        const int mrow1 = mrow0 + 8;
        const int b0i = mrow0 >> 11, s0i = mrow0 & (SEQ - 1);
        const int b1i = mrow1 >> 11, s1i = mrow1 & (SEQ - 1);
#pragma unroll
        for (int j = 0; j < 8; j++) {
            const int ncol = n0 + wn + j * 8 + q * 2;
            const float bi0 = bias[ncol], bi1 = bias[ncol + 1];
            const float c0 = (acc[i][j][0] + bi0) * oscale;
            const float c1 = (acc[i][j][1] + bi1) * oscale;
            const float c2 = (acc[i][j][2] + bi0) * oscale;
            const float c3 = (acc[i][j][3] + bi1) * oscale;
            if (LAYOUT == 0) {
                float* out = (float*)outv;
                *(float2*)&out[(size_t)mrow0 * DMODEL + ncol] = make_float2(c0, c1);
                *(float2*)&out[(size_t)mrow1 * DMODEL + ncol] = make_float2(c2, c3);
            } else if (LAYOUT == 1) {
                __half* out = (__half*)outv;
                const int h = ncol >> 6, dk = ncol & 63;
                __half2 v0 = __floats2half2_rn(c0, c1);
                __half2 v1 = __floats2half2_rn(c2, c3);
                *(__half2*)&out[(((size_t)(b0i * NHEADS + h) * SEQ + s0i) << 6) + dk] = v0;
                *(__half2*)&out[(((size_t)(b1i * NHEADS + h) * SEQ + s1i) << 6) + dk] = v1;
            } else {
                __half* out = (__half*)outv;
                const int h = ncol >> 6, dk = ncol & 63;
                const size_t base = ((size_t)(b0i * NHEADS + h) * DK + dk) * SEQ;
                out[base + s0i]       = __float2half_rn(c0);
                out[base + SEQ + s0i] = __float2half_rn(c1);
                const size_t base1 = ((size_t)(b1i * NHEADS + h) * DK + dk) * SEQ;
                out[base1 + s1i]       = __float2half_rn(c2);
                out[base1 + SEQ + s1i] = __float2half_rn(c3);
            }
        }
    }
}

__global__ __launch_bounds__(256, 1) void qkv_gemm_f16(
    const float* __restrict__ bq, const float* __restrict__ bk,
    const float* __restrict__ bv)
{
    if (blockIdx.z == 0)      gemm_f16_body<1>(g_xh, g_wqt, bq, g_Qh, 0.125f * LOG2E);
    else if (blockIdx.z == 1) gemm_f16_body<1>(g_xh, g_wkt, bk, g_Kh, 1.0f);
    else                      gemm_f16_body<2>(g_xh, g_wvt, bv, g_Vh, 1.0f);
}

__global__ __launch_bounds__(256, 1) void out_gemm_f16(
    const float* __restrict__ bo, float* __restrict__ out)
{
    gemm_f16_body<0>(g_ctxh, g_wot, bo, out, 1.0f);
}

// ---------------- flash attention: ldmatrix + exp2 softmax --------------------
// CTA: 128 queries, key tiles of 64, 8 warps x 16 q-rows, 3-stage KV cp.async.
#define AST 72
#define AQ_H (128 * AST)            // 9216 halves
#define AKV_H (2 * 64 * AST)        // K+V per stage = 9216 halves
#define ANST 3
#define ATT_SMEM (36864 * 2 + SEQ * 4)   // 81920 B

__global__ __launch_bounds__(256, 2) void flash_attn_f16(const int* __restrict__ mask)
{
    extern __shared__ __half smh[];
    __half* KVs = smh + AQ_H;
    int*    Ms = (int*)(smh + AQ_H + ANST * AKV_H);

    const uint32_t smem_u32 = (uint32_t)__cvta_generic_to_shared(smh);
    const uint32_t Qs_u = smem_u32;
    const uint32_t KV_u = smem_u32 + AQ_H * 2;

    const int bh = blockIdx.y;
    const int b  = bh >> 4;
    const int h  = bh & 15;
    const int q0 = blockIdx.x * 128;
    const int tid = threadIdx.x;
    const int warp = tid >> 5, lane = tid & 31;
    const int q = lane & 3;
    const int g = lane >> 2;
    const int wq0 = warp * 16;

    const __half* Qp = g_Qh + (size_t)bh * SEQ * DK + (size_t)q0 * DK;
    const __half* Kp = g_Kh + (size_t)bh * SEQ * DK;
    const __half* Vp = g_Vh + (size_t)bh * DK * SEQ;   // [dk][S]

    // Q tile: 128 rows x 128B = 1024 cp16
#pragma unroll
    for (int i = 0; i < 4; i++) {
        int id = tid + i * 256;
        int r = id >> 3, c = id & 7;
        cp_async16(Qs_u + (uint32_t)(r * (AST * 2) + c * 16),
                   Qp + (size_t)r * DK + c * 8);
    }
    const int* mbase = mask + b * SEQ;
#pragma unroll
    for (int i = 0; i < 8; i++) Ms[tid + i * 256] = mbase[tid + i * 256];

    auto issue_kv = [&](int kt) {
        const int stage = kt % 3;
        const __half* Kpt = Kp + (size_t)kt * 64 * DK;
        const __half* Vpt = Vp + (size_t)kt * 64;
        const uint32_t kb = KV_u + stage * (AKV_H * 2);
        const uint32_t vb = kb + 64 * AST * 2;
#pragma unroll
        for (int i = 0; i < 2; i++) {
            int id = tid + i * 256;
            int r = id >> 3, c = id & 7;
            cp_async16(kb + (uint32_t)(r * (AST * 2) + c * 16),
                       Kpt + (size_t)r * DK + c * 8);
        }
#pragma unroll
        for (int i = 0; i < 2; i++) {
            int id = tid + i * 256;
            int r = id >> 3, c = id & 7;
            cp_async16(vb + (uint32_t)(r * (AST * 2) + c * 16),
                       Vpt + (size_t)r * SEQ + c * 8);
        }
    };

    issue_kv(0); CP_COMMIT();
    issue_kv(1); CP_COMMIT();
    issue_kv(2); CP_COMMIT();

    // ldmatrix lane->address offsets (bytes)
    // Q x4: r0/r1 = rows wq0+0..7 / +8..15 at col lo; r2/r3 = same rows col hi
    const uint32_t q_lane_off =
        (uint32_t)((wq0 + ((lane >> 3) & 1) * 8 + (lane & 7)) * AST + (lane >> 4) * 8) * 2;
    // K/V x4: r0/r1 = tile t rows, col lo/hi; r2/r3 = tile t+1 rows, col lo/hi
    const uint32_t kv_lane_off =
        (uint32_t)(((lane & 7) + (lane >> 4) * 8) * AST + ((lane >> 3) & 1) * 8) * 2;

    float m0 = -1e30f, m1 = -1e30f, l0 = 0.f, l1 = 0.f;
    float o[8][4];
#pragma unroll
    for (int j = 0; j < 8; j++)
#pragma unroll
        for (int c = 0; c < 4; c++) o[j][c] = 0.f;

    const int NKT = SEQ / 64;   // 32
    for (int kt = 0; kt < NKT; kt++) {
        if (kt < NKT - 2)      CP_WAIT(2);
        else if (kt < NKT - 1) CP_WAIT(1);
        else                   CP_WAIT(0);
        __syncthreads();

        const uint32_t Kt_u = KV_u + (kt % 3) * (AKV_H * 2);
        const uint32_t Vt_u = Kt_u + 64 * AST * 2;

        // ---- S = Q @ K^T  (Q pre-scaled by 0.125*log2e) ----
        float s[8][4];
#pragma unroll
        for (int j = 0; j < 8; j++)
#pragma unroll
            for (int c = 0; c < 4; c++) s[j][c] = 0.f;

#pragma unroll
        for (int ks = 0; ks < 4; ks++) {
            uint32_t a0, a1, a2, a3;
            LDSM_X4(a0, a1, a2, a3, Qs_u + q_lane_off + ks * 32);
#pragma unroll
            for (int p = 0; p < 4; p++) {
                uint32_t b00, b01, b10, b11;
                LDSM_X4(b00, b01, b10, b11,
                        Kt_u + kv_lane_off + (uint32_t)(p * 16 * AST) * 2 + ks * 32);
                MMA_F16(s[2*p][0], s[2*p][1], s[2*p][2], s[2*p][3],
                        a0, a1, a2, a3, b00, b01);
                MMA_F16(s[2*p+1][0], s[2*p+1][1], s[2*p+1][2], s[2*p+1][3],
                        a0, a1, a2, a3, b10, b11);
            }
        }

        // ---- mask ----
        const int kbase = kt * 64;
#pragma unroll
        for (int nt = 0; nt < 8; nt++) {
            const int mv0 = Ms[kbase + nt * 8 + 2 * q];
            const int mv1 = Ms[kbase + nt * 8 + 2 * q + 1];
            if (mv0 == 0) { s[nt][0] = -1e9f; s[nt][2] = -1e9f; }
            if (mv1 == 0) { s[nt][1] = -1e9f; s[nt][3] = -1e9f; }
        }

        // ---- online softmax in exp2 domain ----
        float mt0 = s[0][0], mt1 = s[0][2];
#pragma unroll
        for (int nt = 0; nt < 8; nt++) {
            mt0 = fmaxf(mt0, fmaxf(s[nt][0], s[nt][1]));
            mt1 = fmaxf(mt1, fmaxf(s[nt][2], s[nt][3]));
        }
        mt0 = fmaxf(mt0, __shfl_xor_sync(0xffffffffu, mt0, 1));
        mt0 = fmaxf(mt0, __shfl_xor_sync(0xffffffffu, mt0, 2));
        mt1 = fmaxf(mt1, __shfl_xor_sync(0xffffffffu, mt1, 1));
        mt1 = fmaxf(mt1, __shfl_xor_sync(0xffffffffu, mt1, 2));

        const float nm0 = fmaxf(m0, mt0);
        const float nm1 = fmaxf(m1, mt1);
        const float al0 = ex2f(m0 - nm0);
        const float al1 = ex2f(m1 - nm1);
        m0 = nm0; m1 = nm1;

        uint32_t P2[8][2];
        float ls0 = 0.f, ls1 = 0.f;
#pragma unroll
        for (int nt = 0; nt < 8; nt++) {
            float p00 = ex2f(s[nt][0] - nm0);
            float p01 = ex2f(s[nt][1] - nm0);
            float p10 = ex2f(s[nt][2] - nm1);
            float p11 = ex2f(s[nt][3] - nm1);
            ls0 += p00 + p01;
            ls1 += p10 + p11;
            __half2 hh0 = __floats2half2_rn(p00, p01);
            __half2 hh1 = __floats2half2_rn(p10, p11);
            P2[nt][0] = *(uint32_t*)&hh0;
            P2[nt][1] = *(uint32_t*)&hh1;
        }
        ls0 += __shfl_xor_sync(0xffffffffu, ls0, 1);
        ls0 += __shfl_xor_sync(0xffffffffu, ls0, 2);
        ls1 += __shfl_xor_sync(0xffffffffu, ls1, 1);
        ls1 += __shfl_xor_sync(0xffffffffu, ls1, 2);
        l0 = l0 * al0 + ls0;
        l1 = l1 * al1 + ls1;

#pragma unroll
        for (int nt = 0; nt < 8; nt++) {
            o[nt][0] *= al0; o[nt][1] *= al0;
            o[nt][2] *= al1; o[nt][3] *= al1;
        }

        // ---- O += P @ V  (P in registers; V via ldmatrix) ----
#pragma unroll
        for (int ks = 0; ks < 4; ks++) {
            const uint32_t a0 = P2[2 * ks][0];
            const uint32_t a1 = P2[2 * ks][1];
            const uint32_t a2 = P2[2 * ks + 1][0];
            const uint32_t a3 = P2[2 * ks + 1][1];
#pragma unroll
            for (int p = 0; p < 4; p++) {
                uint32_t b00, b01, b10, b11;
                LDSM_X4(b00, b01, b10, b11,
                        Vt_u + kv_lane_off + (uint32_t)(p * 16 * AST) * 2 + ks * 32);
                MMA_F16(o[2*p][0], o[2*p][1], o[2*p][2], o[2*p][3],
                        a0, a1, a2, a3, b00, b01);
                MMA_F16(o[2*p+1][0], o[2*p+1][1], o[2*p+1][2], o[2*p+1][3],
                        a0, a1, a2, a3, b10, b11);
            }
        }

        __syncthreads();   // stage fully consumed before refill

        if (kt + 3 < NKT) {
            issue_kv(kt + 3);
            CP_COMMIT();
        }
    }

    // ---- epilogue: normalize, write ctx fp16 [B,S,D] ----
    const float inv0 = 1.f / l0;
    const float inv1 = 1.f / l1;
    const int row0 = q0 + wq0 + g;
    const int row1 = row0 + 8;
    __half* out0 = g_ctxh + (size_t)(b * SEQ + row0) * DMODEL + h * 64;
    __half* out1 = g_ctxh + (size_t)(b * SEQ + row1) * DMODEL + h * 64;
#pragma unroll
    for (int nt = 0; nt < 8; nt++) {
        const int c = nt * 8 + 2 * q;
        __half2 v0 = __floats2half2_rn(o[nt][0] * inv0, o[nt][1] * inv0);
        __half2 v1 = __floats2half2_rn(o[nt][2] * inv1, o[nt][3] * inv1);
        *(__half2*)&out0[c] = v0;
        *(__half2*)&out1[c] = v1;
    }
}

// ---------------- launch ------------------------------------------------------
extern "C" void kernel_launch(void* const* d_in, const int* in_sizes, int n_in,
                              void* d_out, int out_size)
{
    const float* x  = (const float*)d_in[0];
    const int* mask = (const int*)d_in[1];
    const float* wq = (const float*)d_in[2];
    const float* bq = (const float*)d_in[3];
    const float* wk = (const float*)d_in[4];
    const float* bk = (const float*)d_in[5];
    const float* wv = (const float*)d_in[6];
    const float* bv = (const float*)d_in[7];
    const float* wo = (const float*)d_in[8];
    const float* bo = (const float*)d_in[9];

    __half* d_xh;   cudaGetSymbolAddress((void**)&d_xh, g_xh);
    __half* d_wqt;  cudaGetSymbolAddress((void**)&d_wqt, g_wqt);
    __half* d_wkt;  cudaGetSymbolAddress((void**)&d_wkt, g_wkt);
    __half* d_wvt;  cudaGetSymbolAddress((void**)&d_wvt, g_wvt);
    __half* d_wot;  cudaGetSymbolAddress((void**)&d_wot, g_wot);

    const int nx4 = BATCH * SEQ * DMODEL / 4;
    cvt_f16_kernel<<<(nx4 + 255) / 256, 256>>>(x, d_xh, nx4);
    dim3 tg(DMODEL / 32, DMODEL / 32, 4);
    cvt_transpose4_kernel<<<tg, 256>>>(wq, wk, wv, wo, d_wqt, d_wkt, d_wvt, d_wot);

    // 1) QKV projections (Q epilogue folds 0.125*log2e)
    cudaFuncSetAttribute(qkv_gemm_f16,
                         cudaFuncAttributeMaxDynamicSharedMemorySize, GSMEM);
    dim3 g1(DMODEL / 256, (BATCH * SEQ) / 128, 3);
    qkv_gemm_f16<<<g1, 256, GSMEM>>>(bq, bk, bv);

    // 2) flash attention (ldmatrix + exp2)
    cudaFuncSetAttribute(flash_attn_f16,
                         cudaFuncAttributeMaxDynamicSharedMemorySize, ATT_SMEM);
    flash_attn_f16<<<dim3(SEQ / 128, BATCH * NHEADS), 256, ATT_SMEM>>>(mask);

    // 3) output projection
    cudaFuncSetAttribute(out_gemm_f16,
                         cudaFuncAttributeMaxDynamicSharedMemorySize, GSMEM);
    dim3 g3(DMODEL / 256, (BATCH * SEQ) / 128);
    out_gemm_f16<<<g3, 256, GSMEM>>>(bo, (float*)d_out);
}